// round 8
// baseline (speedup 1.0000x reference)
#include <cuda_runtime.h>
#include <cstdint>

#define NAG   8
#define BATCH 32768
#define SDIM  128
#define ADIM  16
#define HID   128
#define HEADS 4
#define AD    32

// ---------------- scratch (device globals; no allocation allowed) ----------------
__device__ float g_sa   [(size_t)NAG * BATCH * HID];
__device__ float g_se   [(size_t)NAG * BATCH * HID];
__device__ float g_Kb   [(size_t)NAG * BATCH * HID];
__device__ float g_Qb   [(size_t)NAG * BATCH * HID];
__device__ float g_Vb   [(size_t)NAG * BATCH * HID];
__device__ float g_oth  [(size_t)NAG * BATCH * HID];

__device__ __forceinline__ unsigned totf32(float x) {
    unsigned u;
    asm("cvt.rna.tf32.f32 %0, %1;" : "=r"(u) : "f"(x));
    return u;
}

// A smem addressing: word = k*136 + 4*((k>>2)&1) + m  (conflict-free frag loads).
__device__ __forceinline__ int AIDX(int k, int m) {
    return k * 136 + (((k >> 2) & 1) << 2) + m;
}
__device__ __forceinline__ int BIDX(int k, int n) {      // BN=128, stride 136
    return k * 136 + n;
}

#define MMA_TF32(acc, a0, a1, a2, a3, b0, b1)                                     \
    asm("mma.sync.aligned.m16n8k8.row.col.f32.tf32.tf32.f32 "                     \
        "{%0,%1,%2,%3}, {%4,%5,%6,%7}, {%8,%9}, {%0,%1,%2,%3};"                   \
        : "+f"((acc)[0]), "+f"((acc)[1]), "+f"((acc)[2]), "+f"((acc)[3])          \
        : "r"(a0), "r"(a1), "r"(a2), "r"(a3), "r"(b0), "r"(b1))

// ---------------- single-output GEMM (round-4/6 proven config) ---------------------
// 128x128 block, 8 warps 2x4, warp 64x32, KT=16.
__global__ void __launch_bounds__(256)
gemm128_tc(const float* __restrict__ A1, int a1w,
           const float* __restrict__ A2, int a2w,
           const float* __restrict__ W, int headpacked,
           const float* __restrict__ bias, int dorelu,
           float* __restrict__ C, int Ktot)
{
    const int KT = 16, TSZ = 16 * 136;
    __shared__ unsigned As[2][TSZ];
    __shared__ unsigned Bs[2][TSZ];

    int n   = blockIdx.z;
    int b0g = blockIdx.x * 128;
    const float* A1n = A1 + (size_t)n * BATCH * a1w;
    const float* A2n = A2 ? (A2 + (size_t)n * BATCH * a2w) : A1;
    const float* Wn  = headpacked ? W : (W + (size_t)n * Ktot * 128);
    const float* bn  = bias ? (headpacked ? bias : bias + n * 128) : nullptr;
    float* Cn = C + (size_t)n * BATCH * 128;

    int tid  = threadIdx.x;
    int wid  = tid >> 5, lane = tid & 31;
    int grp  = lane >> 2, tig = lane & 3;
    int wm   = (wid >> 2) * 64;
    int wn   = (wid & 3) * 32;

    int arow = tid >> 2;
    int ak   = (tid & 3) << 2;
    int krow = tid >> 4;
    int wcol = (tid & 15) << 3;

    float acc[4][4][4];
    #pragma unroll
    for (int mt = 0; mt < 4; mt++)
        #pragma unroll
        for (int nt = 0; nt < 4; nt++)
            #pragma unroll
            for (int r = 0; r < 4; r++) acc[mt][nt][r] = 0.f;

    int nkt = Ktot >> 4;
    float4 va0, va1, vw0, vw1;

    auto ldtile = [&](int kt) {
        int k0 = kt * KT;
        const float* src; int srcw, kbase;
        if (k0 < a1w) { src = A1n; srcw = a1w; kbase = k0; }
        else          { src = A2n; srcw = a2w; kbase = k0 - a1w; }
        va0 = *(const float4*)(src + (size_t)(b0g + arow)      * srcw + kbase + ak);
        va1 = *(const float4*)(src + (size_t)(b0g + arow + 64) * srcw + kbase + ak);
        const float* wp;
        if (!headpacked) wp = Wn + (size_t)(k0 + krow) * 128 + wcol;
        else             wp = Wn + (size_t)(wcol >> 5) * (HID * AD) + (size_t)(k0 + krow) * AD + (wcol & 31);
        vw0 = *(const float4*)wp;
        vw1 = *(const float4*)(wp + 4);
    };
    auto ststile = [&](int buf) {
        unsigned* Ab = As[buf];
        Ab[AIDX(ak + 0, arow)]      = totf32(va0.x);
        Ab[AIDX(ak + 1, arow)]      = totf32(va0.y);
        Ab[AIDX(ak + 2, arow)]      = totf32(va0.z);
        Ab[AIDX(ak + 3, arow)]      = totf32(va0.w);
        Ab[AIDX(ak + 0, arow + 64)] = totf32(va1.x);
        Ab[AIDX(ak + 1, arow + 64)] = totf32(va1.y);
        Ab[AIDX(ak + 2, arow + 64)] = totf32(va1.z);
        Ab[AIDX(ak + 3, arow + 64)] = totf32(va1.w);
        unsigned* Bb = Bs[buf];
        uint4 w0 = { totf32(vw0.x), totf32(vw0.y), totf32(vw0.z), totf32(vw0.w) };
        uint4 w1 = { totf32(vw1.x), totf32(vw1.y), totf32(vw1.z), totf32(vw1.w) };
        *(uint4*)&Bb[BIDX(krow, wcol)]     = w0;
        *(uint4*)&Bb[BIDX(krow, wcol + 4)] = w1;
    };

    ldtile(0);
    ststile(0);
    __syncthreads();

    for (int kt = 0; kt < nkt; kt++) {
        int buf = kt & 1;
        if (kt + 1 < nkt) ldtile(kt + 1);
        const unsigned* Ab = As[buf];
        const unsigned* Bb = Bs[buf];
        #pragma unroll
        for (int ks = 0; ks < 2; ks++) {
            int k0r = ks * 8 + tig;
            int k4r = ks * 8 + tig + 4;
            unsigned af[4][4];
            #pragma unroll
            for (int mt = 0; mt < 4; mt++) {
                int m = wm + mt * 16 + grp;
                af[mt][0] = Ab[AIDX(k0r, m)];
                af[mt][1] = Ab[AIDX(k0r, m + 8)];
                af[mt][2] = Ab[AIDX(k4r, m)];
                af[mt][3] = Ab[AIDX(k4r, m + 8)];
            }
            unsigned bf[4][2];
            #pragma unroll
            for (int nt = 0; nt < 4; nt++) {
                int c = wn + nt * 8 + grp;
                bf[nt][0] = Bb[BIDX(k0r, c)];
                bf[nt][1] = Bb[BIDX(k4r, c)];
            }
            #pragma unroll
            for (int mt = 0; mt < 4; mt++)
                #pragma unroll
                for (int nt = 0; nt < 4; nt++)
                    MMA_TF32(acc[mt][nt], af[mt][0], af[mt][1], af[mt][2], af[mt][3],
                             bf[nt][0], bf[nt][1]);
        }
        if (kt + 1 < nkt) ststile(buf ^ 1);
        __syncthreads();
    }

    #pragma unroll
    for (int nt = 0; nt < 4; nt++) {
        int col = wn + nt * 8 + tig * 2;
        float bj0 = bn ? bn[col]     : 0.f;
        float bj1 = bn ? bn[col + 1] : 0.f;
        #pragma unroll
        for (int mt = 0; mt < 4; mt++) {
            int row0 = b0g + wm + mt * 16 + grp;
            float v0 = acc[mt][nt][0] + bj0;
            float v1 = acc[mt][nt][1] + bj1;
            float v2 = acc[mt][nt][2] + bj0;
            float v3 = acc[mt][nt][3] + bj1;
            if (dorelu) {
                v0 = fmaxf(v0, 0.f); v1 = fmaxf(v1, 0.f);
                v2 = fmaxf(v2, 0.f); v3 = fmaxf(v3, 0.f);
            }
            *(float2*)&Cn[(size_t)row0 * 128 + col]       = make_float2(v0, v1);
            *(float2*)&Cn[(size_t)(row0 + 8) * 128 + col] = make_float2(v2, v3);
        }
    }
}

// ---------------- dual-output GEMM: [C0 | C1] in one pass --------------------------
// 128x256 block, 512 threads, 16 warps (2x8), warp 64x32, KT=8, A staged once.
// Per 128-wide half: own W (std/headpacked), bias, relu, valid-K (zero-padded past).
__global__ void __launch_bounds__(512)
gemm_dual(const float* __restrict__ A1, int a1w,
          const float* __restrict__ A2, int a2w, int Ktot,
          const float* __restrict__ W0, int hp0, const float* __restrict__ b0v,
          int relu0, float* __restrict__ C0, int km0,
          const float* __restrict__ W1, int hp1, const float* __restrict__ b1v,
          int relu1, float* __restrict__ C1, int km1)
{
    const int KT = 8, STRB = 264;                 // 264 ≡ 8 (mod 32)
    __shared__ unsigned As[2][8 * 136];
    __shared__ unsigned Bs[2][8 * 264];

    int n   = blockIdx.z;
    int b0g = blockIdx.x * 128;
    const float* A1n = A1 + (size_t)n * BATCH * a1w;
    const float* A2n = A2 ? (A2 + (size_t)n * BATCH * a2w) : A1;
    const float* W0n = hp0 ? W0 : (W0 + (size_t)n * km0 * 128);
    const float* W1n = hp1 ? W1 : (W1 + (size_t)n * km1 * 128);
    const float* b0n = b0v ? (hp0 ? b0v : b0v + n * 128) : nullptr;
    const float* b1n = b1v ? (hp1 ? b1v : b1v + n * 128) : nullptr;
    float* C0n = C0 + (size_t)n * BATCH * 128;
    float* C1n = C1 + (size_t)n * BATCH * 128;

    int tid  = threadIdx.x;
    int wid  = tid >> 5, lane = tid & 31;
    int grp  = lane >> 2, tig = lane & 3;
    int wm   = (wid >> 3) * 64;        // 0 / 64
    int wn   = (wid & 7) * 32;         // 0..224

    // staging: A by threads 0..255 (one float4 each), B by all 512
    int arow = tid >> 1;               // 0..255 -> rows 0..127
    int ak   = (tid & 1) << 2;         // 0 / 4
    int krow = tid >> 6;               // 0..7
    int bcol = (tid & 63) << 2;        // 0..252

    float acc[4][4][4];
    #pragma unroll
    for (int mt = 0; mt < 4; mt++)
        #pragma unroll
        for (int nt = 0; nt < 4; nt++)
            #pragma unroll
            for (int r = 0; r < 4; r++) acc[mt][nt][r] = 0.f;

    int nkt = Ktot >> 3;
    float4 va, vw;

    auto ldtile = [&](int kt) {
        int k0 = kt * KT;
        if (tid < 256) {
            const float* src; int srcw, kbase;
            if (k0 < a1w) { src = A1n; srcw = a1w; kbase = k0; }
            else          { src = A2n; srcw = a2w; kbase = k0 - a1w; }
            va = *(const float4*)(src + (size_t)(b0g + arow) * srcw + kbase + ak);
        }
        int k  = k0 + krow;
        int h  = bcol >> 7;
        int lc = bcol & 127;
        const float* Wh = h ? W1n : W0n;
        int hph = h ? hp1 : hp0;
        int kmh = h ? km1 : km0;
        if (k < kmh) {
            const float* wp = hph
                ? Wh + (size_t)(lc >> 5) * (HID * AD) + (size_t)k * AD + (lc & 31)
                : Wh + (size_t)k * 128 + lc;
            vw = *(const float4*)wp;
        } else {
            vw = make_float4(0.f, 0.f, 0.f, 0.f);
        }
    };
    auto ststile = [&](int buf) {
        if (tid < 256) {
            unsigned* Ab = As[buf];
            Ab[AIDX(ak + 0, arow)] = totf32(va.x);
            Ab[AIDX(ak + 1, arow)] = totf32(va.y);
            Ab[AIDX(ak + 2, arow)] = totf32(va.z);
            Ab[AIDX(ak + 3, arow)] = totf32(va.w);
        }
        unsigned* Bb = Bs[buf];
        uint4 u = { totf32(vw.x), totf32(vw.y), totf32(vw.z), totf32(vw.w) };
        *(uint4*)&Bb[krow * STRB + bcol] = u;
    };

    ldtile(0);
    ststile(0);
    __syncthreads();

    for (int kt = 0; kt < nkt; kt++) {
        int buf = kt & 1;
        if (kt + 1 < nkt) ldtile(kt + 1);
        const unsigned* Ab = As[buf];
        const unsigned* Bb = Bs[buf];
        unsigned af[4][4];
        #pragma unroll
        for (int mt = 0; mt < 4; mt++) {
            int m = wm + mt * 16 + grp;
            af[mt][0] = Ab[AIDX(tig, m)];
            af[mt][1] = Ab[AIDX(tig, m + 8)];
            af[mt][2] = Ab[AIDX(tig + 4, m)];
            af[mt][3] = Ab[AIDX(tig + 4, m + 8)];
        }
        unsigned bf[4][2];
        #pragma unroll
        for (int nt = 0; nt < 4; nt++) {
            int c = wn + nt * 8 + grp;
            bf[nt][0] = Bb[tig * STRB + c];
            bf[nt][1] = Bb[(tig + 4) * STRB + c];
        }
        #pragma unroll
        for (int mt = 0; mt < 4; mt++)
            #pragma unroll
            for (int nt = 0; nt < 4; nt++)
                MMA_TF32(acc[mt][nt], af[mt][0], af[mt][1], af[mt][2], af[mt][3],
                         bf[nt][0], bf[nt][1]);
        if (kt + 1 < nkt) ststile(buf ^ 1);
        __syncthreads();
    }

    // epilogue: half-specific bias/relu/output
    int h  = wn >> 7;
    int ln = wn & 127;
    const float* bh = h ? b1n : b0n;
    int rh = h ? relu1 : relu0;
    float* Ch = h ? C1n : C0n;
    #pragma unroll
    for (int nt = 0; nt < 4; nt++) {
        int col = ln + nt * 8 + tig * 2;
        float bj0 = bh ? bh[col]     : 0.f;
        float bj1 = bh ? bh[col + 1] : 0.f;
        #pragma unroll
        for (int mt = 0; mt < 4; mt++) {
            int row0 = b0g + wm + mt * 16 + grp;
            float v0 = acc[mt][nt][0] + bj0;
            float v1 = acc[mt][nt][1] + bj1;
            float v2 = acc[mt][nt][2] + bj0;
            float v3 = acc[mt][nt][3] + bj1;
            if (rh) {
                v0 = fmaxf(v0, 0.f); v1 = fmaxf(v1, 0.f);
                v2 = fmaxf(v2, 0.f); v3 = fmaxf(v3, 0.f);
            }
            *(float2*)&Ch[(size_t)row0 * 128 + col]       = make_float2(v0, v1);
            *(float2*)&Ch[(size_t)(row0 + 8) * 128 + col] = make_float2(v2, v3);
        }
    }
}

// ---------------- fused critic: h1 GEMM (K=256) + all_q + argmax gather -----------
__global__ void __launch_bounds__(256)
critic_tc(const float* __restrict__ actions,
          const float* __restrict__ Wc1, const float* __restrict__ bc1,
          const float* __restrict__ Wc2, const float* __restrict__ bc2,
          float* __restrict__ out)
{
    const int KT = 16, TSZ = 16 * 136;
    __shared__ unsigned As[2][TSZ];
    __shared__ unsigned Bs[2][TSZ];
    __shared__ float Wc2s[128 * 16];
    __shared__ float bc1s[128];
    __shared__ float bc2s[16];
    __shared__ float rowacc[128];
    __shared__ int   amaxs[128];

    int n   = blockIdx.z;
    int b0g = blockIdx.x * 128;
    const float* A1n = g_se  + (size_t)n * BATCH * 128;
    const float* A2n = g_oth + (size_t)n * BATCH * 128;
    const float* Wn  = Wc1 + (size_t)n * 256 * 128;
    const float* Wc2n = Wc2 + (size_t)n * 128 * 16;

    int tid  = threadIdx.x;
    int wid  = tid >> 5, lane = tid & 31;
    int grp  = lane >> 2, tig = lane & 3;
    int wm   = (wid >> 2) * 64;
    int wn   = (wid & 3) * 32;
    int arow = tid >> 2;
    int ak   = (tid & 3) << 2;
    int krow = tid >> 4;
    int wcol = (tid & 15) << 3;

    #pragma unroll
    for (int t = 0; t < 2; t++) {
        int f = tid + t * 256;
        *(float4*)&Wc2s[f * 4] = *(const float4*)&Wc2n[f * 4];
    }
    if (tid < 128) {
        bc1s[tid] = bc1[n * 128 + tid];
        rowacc[tid] = 0.f;
        const float* ap = actions + ((size_t)n * BATCH + b0g + tid) * 16;
        float best = ap[0]; int bi = 0;
        #pragma unroll
        for (int c = 1; c < 16; c++) { float v = ap[c]; if (v > best) { best = v; bi = c; } }
        amaxs[tid] = bi;
    }
    if (tid < 16) bc2s[tid] = bc2[n * 16 + tid];

    float acc[4][4][4];
    #pragma unroll
    for (int mt = 0; mt < 4; mt++)
        #pragma unroll
        for (int nt = 0; nt < 4; nt++)
            #pragma unroll
            for (int r = 0; r < 4; r++) acc[mt][nt][r] = 0.f;

    const int nkt = 16;
    float4 va0, va1, vw0, vw1;

    auto ldtile = [&](int kt) {
        int k0 = kt * KT;
        const float* src = (k0 < 128) ? A1n : A2n;
        int kbase = (k0 < 128) ? k0 : (k0 - 128);
        va0 = *(const float4*)(src + (size_t)(b0g + arow)      * 128 + kbase + ak);
        va1 = *(const float4*)(src + (size_t)(b0g + arow + 64) * 128 + kbase + ak);
        const float* wp = Wn + (size_t)(k0 + krow) * 128 + wcol;
        vw0 = *(const float4*)wp;
        vw1 = *(const float4*)(wp + 4);
    };
    auto ststile = [&](int buf) {
        unsigned* Ab = As[buf];
        Ab[AIDX(ak + 0, arow)]      = totf32(va0.x);
        Ab[AIDX(ak + 1, arow)]      = totf32(va0.y);
        Ab[AIDX(ak + 2, arow)]      = totf32(va0.z);
        Ab[AIDX(ak + 3, arow)]      = totf32(va0.w);
        Ab[AIDX(ak + 0, arow + 64)] = totf32(va1.x);
        Ab[AIDX(ak + 1, arow + 64)] = totf32(va1.y);
        Ab[AIDX(ak + 2, arow + 64)] = totf32(va1.z);
        Ab[AIDX(ak + 3, arow + 64)] = totf32(va1.w);
        unsigned* Bb = Bs[buf];
        uint4 w0 = { totf32(vw0.x), totf32(vw0.y), totf32(vw0.z), totf32(vw0.w) };
        uint4 w1 = { totf32(vw1.x), totf32(vw1.y), totf32(vw1.z), totf32(vw1.w) };
        *(uint4*)&Bb[BIDX(krow, wcol)]     = w0;
        *(uint4*)&Bb[BIDX(krow, wcol + 4)] = w1;
    };

    ldtile(0);
    ststile(0);
    __syncthreads();

    for (int kt = 0; kt < nkt; kt++) {
        int buf = kt & 1;
        if (kt + 1 < nkt) ldtile(kt + 1);
        const unsigned* Ab = As[buf];
        const unsigned* Bb = Bs[buf];
        #pragma unroll
        for (int ks = 0; ks < 2; ks++) {
            int k0r = ks * 8 + tig;
            int k4r = ks * 8 + tig + 4;
            unsigned af[4][4];
            #pragma unroll
            for (int mt = 0; mt < 4; mt++) {
                int m = wm + mt * 16 + grp;
                af[mt][0] = Ab[AIDX(k0r, m)];
                af[mt][1] = Ab[AIDX(k0r, m + 8)];
                af[mt][2] = Ab[AIDX(k4r, m)];
                af[mt][3] = Ab[AIDX(k4r, m + 8)];
            }
            unsigned bf[4][2];
            #pragma unroll
            for (int nt = 0; nt < 4; nt++) {
                int c = wn + nt * 8 + grp;
                bf[nt][0] = Bb[BIDX(k0r, c)];
                bf[nt][1] = Bb[BIDX(k4r, c)];
            }
            #pragma unroll
            for (int mt = 0; mt < 4; mt++)
                #pragma unroll
                for (int nt = 0; nt < 4; nt++)
                    MMA_TF32(acc[mt][nt], af[mt][0], af[mt][1], af[mt][2], af[mt][3],
                             bf[nt][0], bf[nt][1]);
        }
        if (kt + 1 < nkt) ststile(buf ^ 1);
        __syncthreads();
    }

    #pragma unroll
    for (int mt = 0; mt < 4; mt++) {
        int row0 = wm + mt * 16 + grp;
        int a0 = amaxs[row0];
        int a1 = amaxs[row0 + 8];
        float p0 = 0.f, p1 = 0.f;
        #pragma unroll
        for (int nt = 0; nt < 4; nt++) {
            int col = wn + nt * 8 + tig * 2;
            float bj0 = bc1s[col], bj1 = bc1s[col + 1];
            float h00 = fmaxf(acc[mt][nt][0] + bj0, 0.f);
            float h01 = fmaxf(acc[mt][nt][1] + bj1, 0.f);
            float h10 = fmaxf(acc[mt][nt][2] + bj0, 0.f);
            float h11 = fmaxf(acc[mt][nt][3] + bj1, 0.f);
            p0 += h00 * Wc2s[col * 16 + a0] + h01 * Wc2s[(col + 1) * 16 + a0];
            p1 += h10 * Wc2s[col * 16 + a1] + h11 * Wc2s[(col + 1) * 16 + a1];
        }
        p0 += __shfl_xor_sync(0xffffffffu, p0, 1);
        p0 += __shfl_xor_sync(0xffffffffu, p0, 2);
        p1 += __shfl_xor_sync(0xffffffffu, p1, 1);
        p1 += __shfl_xor_sync(0xffffffffu, p1, 2);
        if (tig == 0) {
            atomicAdd(&rowacc[row0], p0);
            atomicAdd(&rowacc[row0 + 8], p1);
        }
    }
    __syncthreads();
    if (tid < 128)
        out[(size_t)n * BATCH + b0g + tid] = rowacc[tid] + bc2s[amaxs[tid]];
}

// ---------------- attention (exact fp32) ------------------------------------------
__global__ void __launch_bounds__(256)
attn_kernel()
{
    __shared__ float Ks[4 * 8 * 128];
    __shared__ float Vs[4 * 8 * 128];
    int tid = threadIdx.x;
    int b0  = blockIdx.x * 4;

    #pragma unroll
    for (int t = 0; t < 4; t++) {
        int f  = tid + t * 256;
        int c4 = f & 31;
        int r  = (f >> 5) & 3;
        int j  = f >> 7;
        size_t g = ((size_t)j * BATCH + b0 + r) * 128 + c4 * 4;
        int s = (r * 8 + j) * 128 + c4 * 4;
        *(float4*)&Ks[s] = *(const float4*)&g_Kb[g];
        *(float4*)&Vs[s] = *(const float4*)&g_Vb[g];
    }
    __syncthreads();

    int hf = tid & 1;
    int i  = (tid >> 1) & 7;
    int k  = (tid >> 4) & 3;
    int r  = tid >> 6;

    float q[16];
    size_t base = ((size_t)i * BATCH + b0 + r) * 128 + k * 32 + hf * 16;
    #pragma unroll
    for (int t = 0; t < 4; t++)
        *(float4*)&q[t * 4] = *(const float4*)&g_Qb[base + t * 4];

    float lg[8];
    #pragma unroll
    for (int j = 0; j < 8; j++) {
        const float* kp = &Ks[(r * 8 + j) * 128 + k * 32 + hf * 16];
        float d = 0.f;
        #pragma unroll
        for (int dd = 0; dd < 16; dd++) d += q[dd] * kp[dd];
        d += __shfl_xor_sync(0xffffffffu, d, 1);
        lg[j] = (j == i) ? -1e9f : d * 0.17677669529663687f;
    }
    float m = lg[0];
    #pragma unroll
    for (int j = 1; j < 8; j++) m = fmaxf(m, lg[j]);
    float ssum = 0.f;
    #pragma unroll
    for (int j = 0; j < 8; j++) { lg[j] = __expf(lg[j] - m); ssum += lg[j]; }
    float inv = 1.f / ssum;

    float acc[16];
    #pragma unroll
    for (int dd = 0; dd < 16; dd++) acc[dd] = 0.f;
    #pragma unroll
    for (int j = 0; j < 8; j++) {
        float p = lg[j] * inv;
        const float* vp = &Vs[(r * 8 + j) * 128 + k * 32 + hf * 16];
        #pragma unroll
        for (int dd = 0; dd < 16; dd++) acc[dd] += p * vp[dd];
    }
    #pragma unroll
    for (int t = 0; t < 4; t++)
        *(float4*)&g_oth[base + t * 4] = *(float4*)&acc[t * 4];
}

// ---------------- launch -----------------------------------------------------------
extern "C" void kernel_launch(void* const* d_in, const int* in_sizes, int n_in,
                              void* d_out, int out_size)
{
    const float* states  = (const float*)d_in[0];
    const float* actions = (const float*)d_in[1];
    const float* We      = (const float*)d_in[2];
    const float* be      = (const float*)d_in[3];
    const float* Wse     = (const float*)d_in[4];
    const float* bs      = (const float*)d_in[5];
    const float* Wk      = (const float*)d_in[6];
    const float* Wq      = (const float*)d_in[7];
    const float* Wv      = (const float*)d_in[8];
    const float* bv      = (const float*)d_in[9];
    const float* Wc1     = (const float*)d_in[10];
    const float* bc1     = (const float*)d_in[11];
    const float* Wc2     = (const float*)d_in[12];
    const float* bc2     = (const float*)d_in[13];
    float* out = (float*)d_out;

    float *p_sa, *p_se, *p_K, *p_Q, *p_V;
    cudaGetSymbolAddress((void**)&p_sa, g_sa);
    cudaGetSymbolAddress((void**)&p_se, g_se);
    cudaGetSymbolAddress((void**)&p_K,  g_Kb);
    cudaGetSymbolAddress((void**)&p_Q,  g_Qb);
    cudaGetSymbolAddress((void**)&p_V,  g_Vb);

    dim3 grid(BATCH / 128, 1, NAG);
    // fused encoders: [sa_enc | s_enc], K=144 (se half zero-padded past k=128)
    gemm_dual<<<grid, 512>>>(states, SDIM, actions, ADIM, SDIM + ADIM,
                             We, 0, be, 1, p_sa, 144,
                             Wse, 0, bs, 1, p_se, 128);
    // fused K|V from sa_enc
    gemm_dual<<<grid, 512>>>(p_sa, HID, nullptr, 0, HID,
                             Wk, 1, nullptr, 0, p_K, 128,
                             Wv, 1, bv, 1, p_V, 128);
    // Q from s_enc
    gemm128_tc<<<grid, 256>>>(p_se, HID, nullptr, 0, Wq, 1, nullptr, 0, p_Q, HID);
    // attention
    attn_kernel<<<BATCH / 4, 256>>>();
    // critic (h1 GEMM + all_q + gather fused)
    critic_tc<<<grid, 256>>>(actions, Wc1, bc1, Wc2, bc2, out);
}

// round 9
// speedup vs baseline: 1.1943x; 1.1943x over previous
#include <cuda_runtime.h>
#include <cuda_fp16.h>
#include <cstdint>

#define NAG   8
#define BATCH 32768
#define SDIM  128
#define ADIM  16
#define HID   128
#define HEADS 4
#define AD    32

// ---------------- scratch: intermediates stored fp16 ------------------------------
__device__ __half g_sa [(size_t)NAG * BATCH * HID];
__device__ __half g_se [(size_t)NAG * BATCH * HID];
__device__ __half g_Kb [(size_t)NAG * BATCH * HID];
__device__ __half g_Qb [(size_t)NAG * BATCH * HID];
__device__ __half g_Vb [(size_t)NAG * BATCH * HID];
__device__ __half g_oth[(size_t)NAG * BATCH * HID];

__device__ __forceinline__ unsigned pkh2(float a, float b) {
    __half2 h = __floats2half2_rn(a, b);      // .x = a (low 16 bits) = lower k index
    return *(unsigned*)&h;
}

// smem row stride: 8 data words (16 halves) + 4 pad = 12 ≡ 12 (mod 32)
// fragment-load banks = (12*grp + tig) mod 32 -> perfect 32-bank bijection.
#define SROW 12

#define MMA16(acc, a0, a1, a2, a3, b0, b1)                                        \
    asm("mma.sync.aligned.m16n8k16.row.col.f32.f16.f16.f32 "                      \
        "{%0,%1,%2,%3}, {%4,%5,%6,%7}, {%8,%9}, {%0,%1,%2,%3};"                   \
        : "+f"((acc)[0]), "+f"((acc)[1]), "+f"((acc)[2]), "+f"((acc)[3])          \
        : "r"(a0), "r"(a1), "r"(a2), "r"(a3), "r"(b0), "r"(b1))

// ---------------- fp16 tensor-core GEMM (fp32 accumulate) --------------------------
// C[n] (fp16) = act([A1|A2] @ W[n] + b).  A fp32 or fp16 (a_half flag).
// Block 128x128, 8 warps 2x4, warp 64x32 = 4x4 m16n8k16 tiles, KT=16, dbl buffer.
__global__ void __launch_bounds__(256)
gemm16(const void* __restrict__ A1v, int a1w,
       const void* __restrict__ A2v, int a2w, int a_half,
       const float* __restrict__ W, int headpacked,
       const float* __restrict__ bias, int dorelu,
       __half* __restrict__ C, int Ktot)
{
    __shared__ __align__(16) unsigned As[2][128 * SROW];
    __shared__ __align__(16) unsigned Bs[2][128 * SROW];
    __shared__ float biass[128];

    int n   = blockIdx.z;
    int b0g = blockIdx.x * 128;
    int tid = threadIdx.x;
    int wid = tid >> 5, lane = tid & 31;
    int grp = lane >> 2, tig = lane & 3;
    int wm  = (wid >> 2) * 64;
    int wn  = (wid & 3) * 32;

    int am  = tid >> 1, ahs = tid & 1;      // A staging: row, 8-elem half-select
    int bkp = tid & 7,  bn0 = (tid >> 3) << 2;  // B staging: k-pair, n base

    const float* Wn = headpacked ? W : (W + (size_t)n * Ktot * 128);
    if (tid < 128) {
        const float* bn_ = bias ? (headpacked ? bias : bias + n * 128) : nullptr;
        biass[tid] = bn_ ? bn_[tid] : 0.f;
    }

    float acc[4][4][4];
    #pragma unroll
    for (int mt = 0; mt < 4; mt++)
        #pragma unroll
        for (int nt = 0; nt < 4; nt++)
            #pragma unroll
            for (int r = 0; r < 4; r++) acc[mt][nt][r] = 0.f;

    int nkt = Ktot >> 4;
    uint4 raA;                 // fp16 A prefetch
    float4 fa0, fa1;           // fp32 A prefetch
    float4 w0, w1;             // B prefetch (rows k, k+1)

    auto ldtile = [&](int kt) {
        int k0 = kt * 16;
        int k  = k0 + ahs * 8;
        if (a_half) {
            const __half* src; int w_, kb;
            if (k < a1w) { src = (const __half*)A1v + (size_t)n * BATCH * a1w; w_ = a1w; kb = k; }
            else         { src = (const __half*)A2v + (size_t)n * BATCH * a2w; w_ = a2w; kb = k - a1w; }
            raA = *(const uint4*)(src + (size_t)(b0g + am) * w_ + kb);
        } else {
            const float* src; int w_, kb;
            if (k < a1w) { src = (const float*)A1v + (size_t)n * BATCH * a1w; w_ = a1w; kb = k; }
            else         { src = (const float*)A2v + (size_t)n * BATCH * a2w; w_ = a2w; kb = k - a1w; }
            fa0 = *(const float4*)(src + (size_t)(b0g + am) * w_ + kb);
            fa1 = *(const float4*)(src + (size_t)(b0g + am) * w_ + kb + 4);
        }
        int ka = k0 + 2 * bkp;
        const float *wpa, *wpb;
        if (!headpacked) {
            wpa = Wn + (size_t)ka * 128 + bn0;
            wpb = Wn + (size_t)(ka + 1) * 128 + bn0;
        } else {
            const float* hb = Wn + (size_t)(bn0 >> 5) * (HID * AD) + (bn0 & 31);
            wpa = hb + (size_t)ka * AD;
            wpb = hb + (size_t)(ka + 1) * AD;
        }
        w0 = *(const float4*)wpa;
        w1 = *(const float4*)wpb;
    };
    auto ststile = [&](int buf) {
        unsigned* Ab = As[buf];
        if (a_half) {
            *(uint4*)&Ab[am * SROW + ahs * 4] = raA;
        } else {
            uint4 u;
            u.x = pkh2(fa0.x, fa0.y); u.y = pkh2(fa0.z, fa0.w);
            u.z = pkh2(fa1.x, fa1.y); u.w = pkh2(fa1.z, fa1.w);
            *(uint4*)&Ab[am * SROW + ahs * 4] = u;
        }
        unsigned* Bb = Bs[buf];       // transpose: (k,k+1) pairs scattered to n rows
        Bb[(bn0 + 0) * SROW + bkp] = pkh2(w0.x, w1.x);
        Bb[(bn0 + 1) * SROW + bkp] = pkh2(w0.y, w1.y);
        Bb[(bn0 + 2) * SROW + bkp] = pkh2(w0.z, w1.z);
        Bb[(bn0 + 3) * SROW + bkp] = pkh2(w0.w, w1.w);
    };

    ldtile(0);
    ststile(0);
    __syncthreads();

    for (int kt = 0; kt < nkt; kt++) {
        int buf = kt & 1;
        if (kt + 1 < nkt) ldtile(kt + 1);
        const unsigned* Ab = As[buf];
        const unsigned* Bb = Bs[buf];
        unsigned af[4][4];
        #pragma unroll
        for (int mt = 0; mt < 4; mt++) {
            int m = wm + mt * 16 + grp;
            af[mt][0] = Ab[m * SROW + tig];
            af[mt][1] = Ab[(m + 8) * SROW + tig];
            af[mt][2] = Ab[m * SROW + tig + 4];
            af[mt][3] = Ab[(m + 8) * SROW + tig + 4];
        }
        unsigned bf[4][2];
        #pragma unroll
        for (int nt = 0; nt < 4; nt++) {
            int c = wn + nt * 8 + grp;
            bf[nt][0] = Bb[c * SROW + tig];
            bf[nt][1] = Bb[c * SROW + tig + 4];
        }
        #pragma unroll
        for (int mt = 0; mt < 4; mt++)
            #pragma unroll
            for (int nt = 0; nt < 4; nt++)
                MMA16(acc[mt][nt], af[mt][0], af[mt][1], af[mt][2], af[mt][3],
                      bf[nt][0], bf[nt][1]);
        if (kt + 1 < nkt) ststile(buf ^ 1);
        __syncthreads();
    }

    __half* Cn = C + (size_t)n * BATCH * 128;
    #pragma unroll
    for (int nt = 0; nt < 4; nt++) {
        int col = wn + nt * 8 + tig * 2;
        float bj0 = biass[col], bj1 = biass[col + 1];
        #pragma unroll
        for (int mt = 0; mt < 4; mt++) {
            int row0 = b0g + wm + mt * 16 + grp;
            float v0 = acc[mt][nt][0] + bj0;
            float v1 = acc[mt][nt][1] + bj1;
            float v2 = acc[mt][nt][2] + bj0;
            float v3 = acc[mt][nt][3] + bj1;
            if (dorelu) {
                v0 = fmaxf(v0, 0.f); v1 = fmaxf(v1, 0.f);
                v2 = fmaxf(v2, 0.f); v3 = fmaxf(v3, 0.f);
            }
            *(__half2*)&Cn[(size_t)row0 * 128 + col]       = __floats2half2_rn(v0, v1);
            *(__half2*)&Cn[(size_t)(row0 + 8) * 128 + col] = __floats2half2_rn(v2, v3);
        }
    }
}

// ---------------- fused critic: h1 GEMM (K=256, fp16 A) + all_q + gather ----------
__global__ void __launch_bounds__(256)
critic16(const float* __restrict__ actions,
         const float* __restrict__ Wc1, const float* __restrict__ bc1,
         const float* __restrict__ Wc2, const float* __restrict__ bc2,
         float* __restrict__ out)
{
    __shared__ __align__(16) unsigned As[2][128 * SROW];
    __shared__ __align__(16) unsigned Bs[2][128 * SROW];
    __shared__ float Wc2s[128 * 16];
    __shared__ float bc1s[128];
    __shared__ float bc2s[16];
    __shared__ float rowacc[128];
    __shared__ int   amaxs[128];

    int n   = blockIdx.z;
    int b0g = blockIdx.x * 128;
    int tid = threadIdx.x;
    int wid = tid >> 5, lane = tid & 31;
    int grp = lane >> 2, tig = lane & 3;
    int wm  = (wid >> 2) * 64;
    int wn  = (wid & 3) * 32;
    int am  = tid >> 1, ahs = tid & 1;
    int bkp = tid & 7,  bn0 = (tid >> 3) << 2;

    const __half* A1n = g_se  + (size_t)n * BATCH * 128;
    const __half* A2n = g_oth + (size_t)n * BATCH * 128;
    const float*  Wn  = Wc1 + (size_t)n * 256 * 128;
    const float*  Wc2n = Wc2 + (size_t)n * 128 * 16;

    #pragma unroll
    for (int t = 0; t < 2; t++) {
        int f = tid + t * 256;
        *(float4*)&Wc2s[f * 4] = *(const float4*)&Wc2n[f * 4];
    }
    if (tid < 128) {
        bc1s[tid] = bc1[n * 128 + tid];
        rowacc[tid] = 0.f;
        const float* ap = actions + ((size_t)n * BATCH + b0g + tid) * 16;
        float best = ap[0]; int bi = 0;
        #pragma unroll
        for (int c = 1; c < 16; c++) { float v = ap[c]; if (v > best) { best = v; bi = c; } }
        amaxs[tid] = bi;
    }
    if (tid < 16) bc2s[tid] = bc2[n * 16 + tid];

    float acc[4][4][4];
    #pragma unroll
    for (int mt = 0; mt < 4; mt++)
        #pragma unroll
        for (int nt = 0; nt < 4; nt++)
            #pragma unroll
            for (int r = 0; r < 4; r++) acc[mt][nt][r] = 0.f;

    const int nkt = 16;   // K = 256
    uint4 raA; float4 w0, w1;

    auto ldtile = [&](int kt) {
        int k0 = kt * 16;
        int k  = k0 + ahs * 8;
        const __half* src = (k < 128) ? A1n : A2n;
        int kb = (k < 128) ? k : (k - 128);
        raA = *(const uint4*)(src + (size_t)(b0g + am) * 128 + kb);
        int ka = k0 + 2 * bkp;
        w0 = *(const float4*)(Wn + (size_t)ka * 128 + bn0);
        w1 = *(const float4*)(Wn + (size_t)(ka + 1) * 128 + bn0);
    };
    auto ststile = [&](int buf) {
        *(uint4*)&As[buf][am * SROW + ahs * 4] = raA;
        unsigned* Bb = Bs[buf];
        Bb[(bn0 + 0) * SROW + bkp] = pkh2(w0.x, w1.x);
        Bb[(bn0 + 1) * SROW + bkp] = pkh2(w0.y, w1.y);
        Bb[(bn0 + 2) * SROW + bkp] = pkh2(w0.z, w1.z);
        Bb[(bn0 + 3) * SROW + bkp] = pkh2(w0.w, w1.w);
    };

    ldtile(0);
    ststile(0);
    __syncthreads();

    for (int kt = 0; kt < nkt; kt++) {
        int buf = kt & 1;
        if (kt + 1 < nkt) ldtile(kt + 1);
        const unsigned* Ab = As[buf];
        const unsigned* Bb = Bs[buf];
        unsigned af[4][4];
        #pragma unroll
        for (int mt = 0; mt < 4; mt++) {
            int m = wm + mt * 16 + grp;
            af[mt][0] = Ab[m * SROW + tig];
            af[mt][1] = Ab[(m + 8) * SROW + tig];
            af[mt][2] = Ab[m * SROW + tig + 4];
            af[mt][3] = Ab[(m + 8) * SROW + tig + 4];
        }
        unsigned bf[4][2];
        #pragma unroll
        for (int nt = 0; nt < 4; nt++) {
            int c = wn + nt * 8 + grp;
            bf[nt][0] = Bb[c * SROW + tig];
            bf[nt][1] = Bb[c * SROW + tig + 4];
        }
        #pragma unroll
        for (int mt = 0; mt < 4; mt++)
            #pragma unroll
            for (int nt = 0; nt < 4; nt++)
                MMA16(acc[mt][nt], af[mt][0], af[mt][1], af[mt][2], af[mt][3],
                      bf[nt][0], bf[nt][1]);
        if (kt + 1 < nkt) ststile(buf ^ 1);
        __syncthreads();
    }

    // fused epilogue: relu(h1)·Wc2[:,a] partial dots, quad-reduce, smem add
    #pragma unroll
    for (int mt = 0; mt < 4; mt++) {
        int row0 = wm + mt * 16 + grp;
        int a0 = amaxs[row0];
        int a1 = amaxs[row0 + 8];
        float p0 = 0.f, p1 = 0.f;
        #pragma unroll
        for (int nt = 0; nt < 4; nt++) {
            int col = wn + nt * 8 + tig * 2;
            float bj0 = bc1s[col], bj1 = bc1s[col + 1];
            float h00 = fmaxf(acc[mt][nt][0] + bj0, 0.f);
            float h01 = fmaxf(acc[mt][nt][1] + bj1, 0.f);
            float h10 = fmaxf(acc[mt][nt][2] + bj0, 0.f);
            float h11 = fmaxf(acc[mt][nt][3] + bj1, 0.f);
            p0 += h00 * Wc2s[col * 16 + a0] + h01 * Wc2s[(col + 1) * 16 + a0];
            p1 += h10 * Wc2s[col * 16 + a1] + h11 * Wc2s[(col + 1) * 16 + a1];
        }
        p0 += __shfl_xor_sync(0xffffffffu, p0, 1);
        p0 += __shfl_xor_sync(0xffffffffu, p0, 2);
        p1 += __shfl_xor_sync(0xffffffffu, p1, 1);
        p1 += __shfl_xor_sync(0xffffffffu, p1, 2);
        if (tig == 0) {
            atomicAdd(&rowacc[row0], p0);
            atomicAdd(&rowacc[row0 + 8], p1);
        }
    }
    __syncthreads();
    if (tid < 128)
        out[(size_t)n * BATCH + b0g + tid] = rowacc[tid] + bc2s[amaxs[tid]];
}

// ---------------- attention (fp32 math on fp16 inputs) -----------------------------
__global__ void __launch_bounds__(256)
attn_kernel()
{
    __shared__ float Ks[4 * 8 * 128];
    __shared__ float Vs[4 * 8 * 128];
    int tid = threadIdx.x;
    int b0  = blockIdx.x * 4;

    #pragma unroll
    for (int t = 0; t < 2; t++) {
        int f  = tid + t * 256;            // 0..511 uint4-chunks per array
        int c8 = f & 15;                   // 8-half chunk within 128-col row
        int rj = f >> 4;                   // 0..31
        int r  = rj & 3, j = rj >> 2;
        size_t g = ((size_t)j * BATCH + b0 + r) * 128 + c8 * 8;
        int s = (r * 8 + j) * 128 + c8 * 8;
        uint4 uk = *(const uint4*)(g_Kb + g);
        uint4 uv = *(const uint4*)(g_Vb + g);
        const __half2* hk = (const __half2*)&uk;
        const __half2* hv = (const __half2*)&uv;
        #pragma unroll
        for (int p = 0; p < 4; p++) {
            float2 fk = __half22float2(hk[p]);
            float2 fv = __half22float2(hv[p]);
            Ks[s + p * 2]     = fk.x;
            Ks[s + p * 2 + 1] = fk.y;
            Vs[s + p * 2]     = fv.x;
            Vs[s + p * 2 + 1] = fv.y;
        }
    }
    __syncthreads();

    int hf = tid & 1;
    int i  = (tid >> 1) & 7;
    int k  = (tid >> 4) & 3;
    int r  = tid >> 6;

    float q[16];
    size_t base = ((size_t)i * BATCH + b0 + r) * 128 + k * 32 + hf * 16;
    {
        uint4 u0 = *(const uint4*)(g_Qb + base);
        uint4 u1 = *(const uint4*)(g_Qb + base + 8);
        const __half2* h0 = (const __half2*)&u0;
        const __half2* h1 = (const __half2*)&u1;
        #pragma unroll
        for (int p = 0; p < 4; p++) {
            float2 f0 = __half22float2(h0[p]);
            float2 f1 = __half22float2(h1[p]);
            q[p * 2] = f0.x; q[p * 2 + 1] = f0.y;
            q[8 + p * 2] = f1.x; q[8 + p * 2 + 1] = f1.y;
        }
    }

    float lg[8];
    #pragma unroll
    for (int j = 0; j < 8; j++) {
        const float* kp = &Ks[(r * 8 + j) * 128 + k * 32 + hf * 16];
        float d = 0.f;
        #pragma unroll
        for (int dd = 0; dd < 16; dd++) d += q[dd] * kp[dd];
        d += __shfl_xor_sync(0xffffffffu, d, 1);
        lg[j] = (j == i) ? -1e9f : d * 0.17677669529663687f;
    }
    float m = lg[0];
    #pragma unroll
    for (int j = 1; j < 8; j++) m = fmaxf(m, lg[j]);
    float ssum = 0.f;
    #pragma unroll
    for (int j = 0; j < 8; j++) { lg[j] = __expf(lg[j] - m); ssum += lg[j]; }
    float inv = 1.f / ssum;

    float acc[16];
    #pragma unroll
    for (int dd = 0; dd < 16; dd++) acc[dd] = 0.f;
    #pragma unroll
    for (int j = 0; j < 8; j++) {
        float p = lg[j] * inv;
        const float* vp = &Vs[(r * 8 + j) * 128 + k * 32 + hf * 16];
        #pragma unroll
        for (int dd = 0; dd < 16; dd++) acc[dd] += p * vp[dd];
    }
    {
        uint4 u0, u1;
        unsigned* w0 = (unsigned*)&u0;
        unsigned* w1 = (unsigned*)&u1;
        #pragma unroll
        for (int p = 0; p < 4; p++) {
            w0[p] = pkh2(acc[p * 2], acc[p * 2 + 1]);
            w1[p] = pkh2(acc[8 + p * 2], acc[8 + p * 2 + 1]);
        }
        *(uint4*)(g_oth + base)     = u0;
        *(uint4*)(g_oth + base + 8) = u1;
    }
}

// ---------------- launch -----------------------------------------------------------
extern "C" void kernel_launch(void* const* d_in, const int* in_sizes, int n_in,
                              void* d_out, int out_size)
{
    const float* states  = (const float*)d_in[0];
    const float* actions = (const float*)d_in[1];
    const float* We      = (const float*)d_in[2];
    const float* be      = (const float*)d_in[3];
    const float* Wse     = (const float*)d_in[4];
    const float* bs      = (const float*)d_in[5];
    const float* Wk      = (const float*)d_in[6];
    const float* Wq      = (const float*)d_in[7];
    const float* Wv      = (const float*)d_in[8];
    const float* bv      = (const float*)d_in[9];
    const float* Wc1     = (const float*)d_in[10];
    const float* bc1     = (const float*)d_in[11];
    const float* Wc2     = (const float*)d_in[12];
    const float* bc2     = (const float*)d_in[13];
    float* out = (float*)d_out;

    __half *p_sa, *p_se, *p_K, *p_Q, *p_V;
    cudaGetSymbolAddress((void**)&p_sa, g_sa);
    cudaGetSymbolAddress((void**)&p_se, g_se);
    cudaGetSymbolAddress((void**)&p_K,  g_Kb);
    cudaGetSymbolAddress((void**)&p_Q,  g_Qb);
    cudaGetSymbolAddress((void**)&p_V,  g_Vb);

    dim3 grid(BATCH / 128, 1, NAG);
    gemm16<<<grid, 256>>>(states, SDIM, actions, ADIM, 0, We, 0, be, 1, p_sa, SDIM + ADIM);
    gemm16<<<grid, 256>>>(states, SDIM, nullptr, 0,    0, Wse, 0, bs, 1, p_se, SDIM);
    gemm16<<<grid, 256>>>(p_sa, HID, nullptr, 0, 1, Wk, 1, nullptr, 0, p_K, HID);
    gemm16<<<grid, 256>>>(p_se, HID, nullptr, 0, 1, Wq, 1, nullptr, 0, p_Q, HID);
    gemm16<<<grid, 256>>>(p_sa, HID, nullptr, 0, 1, Wv, 1, bv,      1, p_V, HID);
    attn_kernel<<<BATCH / 4, 256>>>();
    critic16<<<grid, 256>>>(actions, Wc1, bc1, Wc2, bc2, out);
}

// round 11
// speedup vs baseline: 1.6488x; 1.3806x over previous
#include <cuda_runtime.h>
#include <cuda_fp16.h>
#include <cstdint>

#define NAG   8
#define BATCH 32768
#define SDIM  128
#define ADIM  16
#define HID   128
#define HEADS 4
#define AD    32

// ---------------- scratch (device globals; no allocation allowed) ----------------
__device__ __half g_sa [(size_t)NAG * BATCH * HID];
__device__ __half g_se [(size_t)NAG * BATCH * HID];
__device__ __half g_Kb [(size_t)NAG * BATCH * HID];
__device__ __half g_Qb [(size_t)NAG * BATCH * HID];
__device__ __half g_Vb [(size_t)NAG * BATCH * HID];
__device__ __half g_oth[(size_t)NAG * BATCH * HID];
// fp16 copies of inputs / transposed weights ([n][k] layout)
__device__ __half g_sth[(size_t)NAG * BATCH * SDIM];
__device__ __half g_ach[(size_t)NAG * BATCH * ADIM];
__device__ __half g_Wet [NAG * 128 * 144];
__device__ __half g_Wst [NAG * 128 * 128];
__device__ __half g_Wkt [128 * 128];
__device__ __half g_Wqt [128 * 128];
__device__ __half g_Wvt [128 * 128];
__device__ __half g_Wc1t[NAG * 128 * 256];

__device__ __forceinline__ unsigned pkh2(float a, float b) {
    __half2 h = __floats2half2_rn(a, b);
    return *(unsigned*)&h;
}

#define SROW 12          // 8 data words (16 halves) + 4 pad; frag banks bijective
#define STAGES 3

#define MMA16(acc, a0, a1, a2, a3, b0, b1)                                        \
    asm("mma.sync.aligned.m16n8k16.row.col.f32.f16.f16.f32 "                      \
        "{%0,%1,%2,%3}, {%4,%5,%6,%7}, {%8,%9}, {%0,%1,%2,%3};"                   \
        : "+f"((acc)[0]), "+f"((acc)[1]), "+f"((acc)[2]), "+f"((acc)[3])          \
        : "r"(a0), "r"(a1), "r"(a2), "r"(a3), "r"(b0), "r"(b1))

#define CPA16(dst, src) \
    asm volatile("cp.async.cg.shared.global [%0], [%1], 16;\n" :: "r"(dst), "l"(src))
#define CP_COMMIT()  asm volatile("cp.async.commit_group;\n")
#define CP_WAIT1()   asm volatile("cp.async.wait_group 1;\n")
#define CP_WAIT0()   asm volatile("cp.async.wait_group 0;\n")

// ---------------- prep: fp32 -> fp16 input copies ----------------------------------
__global__ void cvt_inputs(const float* __restrict__ states,
                           const float* __restrict__ actions)
{
    size_t i  = (size_t)blockIdx.x * blockDim.x + threadIdx.x;
    size_t ns = (size_t)NAG * BATCH * SDIM / 8;
    size_t na = (size_t)NAG * BATCH * ADIM / 8;
    if (i < ns) {
        const float4* s = (const float4*)states + i * 2;
        float4 a = s[0], b = s[1];
        uint4 u = { pkh2(a.x, a.y), pkh2(a.z, a.w), pkh2(b.x, b.y), pkh2(b.z, b.w) };
        *(uint4*)(g_sth + i * 8) = u;
    } else if (i < ns + na) {
        size_t j = i - ns;
        const float4* s = (const float4*)actions + j * 2;
        float4 a = s[0], b = s[1];
        uint4 u = { pkh2(a.x, a.y), pkh2(a.z, a.w), pkh2(b.x, b.y), pkh2(b.z, b.w) };
        *(uint4*)(g_ach + j * 8) = u;
    }
}

// ---------------- prep: weights -> transposed fp16 [n][k] --------------------------
__global__ void prep_weights(const float* __restrict__ We, const float* __restrict__ Ws,
                             const float* __restrict__ Wk, const float* __restrict__ Wq,
                             const float* __restrict__ Wv, const float* __restrict__ Wc1)
{
    int i = blockIdx.x * 256 + threadIdx.x;
    const int nWe = NAG * 128 * 144;
    const int nWs = NAG * 128 * 128;
    const int nH  = 128 * 128;
    const int nWc = NAG * 128 * 256;
    if (i < nWe) {
        int n = i / (128 * 144), r = i % (128 * 144);
        int c = r / 144, k = r % 144;
        g_Wet[i] = __float2half_rn(We[((size_t)n * 144 + k) * 128 + c]);
    } else if (i < nWe + nWs) {
        int j = i - nWe;
        int n = j / (128 * 128), r = j % (128 * 128);
        int c = r / 128, k = r % 128;
        g_Wst[j] = __float2half_rn(Ws[((size_t)n * 128 + k) * 128 + c]);
    } else if (i < nWe + nWs + 3 * nH) {
        int j = i - nWe - nWs;
        int which = j / nH, r = j % nH;
        int c = r / 128, k = r % 128;
        const float* W = which == 0 ? Wk : (which == 1 ? Wq : Wv);
        __half* D = which == 0 ? g_Wkt : (which == 1 ? g_Wqt : g_Wvt);
        D[r] = __float2half_rn(W[(size_t)(c >> 5) * (HID * AD) + (size_t)k * AD + (c & 31)]);
    } else if (i < nWe + nWs + 3 * nH + nWc) {
        int j = i - nWe - nWs - 3 * nH;
        int n = j / (128 * 256), r = j % (128 * 256);
        int c = r / 256, k = r % 256;
        g_Wc1t[j] = __float2half_rn(Wc1[((size_t)n * 256 + k) * 128 + c]);
    }
}

// ---------------- pipelined fp16 GEMM (cp.async, 3 stages) -------------------------
// C[n] (fp16) = act([A1|A2] @ Wt^T + b).  Wt fp16 [128 n][Ktot k]; wsh: shared
// across agents.  Block 128x128, 8 warps 2x4, warp 64x32, KT=16.
__global__ void __launch_bounds__(256)
gemm16p(const __half* __restrict__ A1, int a1w,
        const __half* __restrict__ A2, int a2w,
        const __half* __restrict__ Wt, int wsh,
        const float* __restrict__ bias, int bsh, int dorelu,
        __half* __restrict__ C, int Ktot)
{
    __shared__ __align__(16) unsigned As[STAGES][128 * SROW];
    __shared__ __align__(16) unsigned Bs[STAGES][128 * SROW];
    __shared__ float biass[128];

    int n   = blockIdx.z;
    int b0g = blockIdx.x * 128;
    int tid = threadIdx.x;
    int wid = tid >> 5, lane = tid & 31;
    int grp = lane >> 2, tig = lane & 3;
    int wm  = (wid >> 2) * 64;
    int wn  = (wid & 3) * 32;
    int am  = tid >> 1, ahs = tid & 1;

    const __half* A1n = A1 + (size_t)n * BATCH * a1w;
    const __half* A2n = A2 ? (A2 + (size_t)n * BATCH * a2w) : A1n;
    const __half* Wtn = wsh ? Wt : (Wt + (size_t)n * 128 * Ktot);
    if (tid < 128) {
        const float* bp = bias ? (bsh ? bias : bias + n * 128) : nullptr;
        biass[tid] = bp ? bp[tid] : 0.f;
    }

    uint32_t sA = (uint32_t)__cvta_generic_to_shared(&As[0][0]);
    uint32_t sB = (uint32_t)__cvta_generic_to_shared(&Bs[0][0]);

    auto fill = [&](int kt) {
        int s  = kt % STAGES;
        int k  = kt * 16 + ahs * 8;
        const __half* asrc;
        if (k < a1w) asrc = A1n + (size_t)(b0g + am) * a1w + k;
        else         asrc = A2n + (size_t)(b0g + am) * a2w + (k - a1w);
        CPA16(sA + (s * 128 * SROW + am * SROW + ahs * 4) * 4, asrc);
        const __half* bsrc = Wtn + (size_t)am * Ktot + k;
        CPA16(sB + (s * 128 * SROW + am * SROW + ahs * 4) * 4, bsrc);
        CP_COMMIT();
    };

    float acc[4][4][4];
    #pragma unroll
    for (int mt = 0; mt < 4; mt++)
        #pragma unroll
        for (int nt = 0; nt < 4; nt++)
            #pragma unroll
            for (int r = 0; r < 4; r++) acc[mt][nt][r] = 0.f;

    int nkt = Ktot >> 4;
    fill(0);
    fill(1);

    for (int kt = 0; kt < nkt; kt++) {
        if (kt + 1 < nkt) { CP_WAIT1(); } else { CP_WAIT0(); }  // drain fix
        __syncthreads();
        const unsigned* Ab = As[kt % STAGES];
        const unsigned* Bb = Bs[kt % STAGES];
        unsigned af[4][4];
        #pragma unroll
        for (int mt = 0; mt < 4; mt++) {
            int m = wm + mt * 16 + grp;
            af[mt][0] = Ab[m * SROW + tig];
            af[mt][1] = Ab[(m + 8) * SROW + tig];
            af[mt][2] = Ab[m * SROW + tig + 4];
            af[mt][3] = Ab[(m + 8) * SROW + tig + 4];
        }
        unsigned bf[4][2];
        #pragma unroll
        for (int nt = 0; nt < 4; nt++) {
            int c = wn + nt * 8 + grp;
            bf[nt][0] = Bb[c * SROW + tig];
            bf[nt][1] = Bb[c * SROW + tig + 4];
        }
        #pragma unroll
        for (int mt = 0; mt < 4; mt++)
            #pragma unroll
            for (int nt = 0; nt < 4; nt++)
                MMA16(acc[mt][nt], af[mt][0], af[mt][1], af[mt][2], af[mt][3],
                      bf[nt][0], bf[nt][1]);
        if (kt + 2 < nkt) fill(kt + 2);
    }

    __half* Cn = C + (size_t)n * BATCH * 128;
    #pragma unroll
    for (int nt = 0; nt < 4; nt++) {
        int col = wn + nt * 8 + tig * 2;
        float bj0 = biass[col], bj1 = biass[col + 1];
        #pragma unroll
        for (int mt = 0; mt < 4; mt++) {
            int row0 = b0g + wm + mt * 16 + grp;
            float v0 = acc[mt][nt][0] + bj0;
            float v1 = acc[mt][nt][1] + bj1;
            float v2 = acc[mt][nt][2] + bj0;
            float v3 = acc[mt][nt][3] + bj1;
            if (dorelu) {
                v0 = fmaxf(v0, 0.f); v1 = fmaxf(v1, 0.f);
                v2 = fmaxf(v2, 0.f); v3 = fmaxf(v3, 0.f);
            }
            *(__half2*)&Cn[(size_t)row0 * 128 + col]       = __floats2half2_rn(v0, v1);
            *(__half2*)&Cn[(size_t)(row0 + 8) * 128 + col] = __floats2half2_rn(v2, v3);
        }
    }
}

// ---------------- pipelined fused critic: h1 GEMM (K=256) + all_q + gather --------
__global__ void __launch_bounds__(256)
critic16p(const float* __restrict__ actions,
          const float* __restrict__ bc1, const float* __restrict__ Wc2,
          const float* __restrict__ bc2, float* __restrict__ out)
{
    __shared__ __align__(16) unsigned As[STAGES][128 * SROW];
    __shared__ __align__(16) unsigned Bs[STAGES][128 * SROW];
    __shared__ float Wc2s[128 * 16];
    __shared__ float bc1s[128];
    __shared__ float bc2s[16];
    __shared__ float rowacc[128];
    __shared__ int   amaxs[128];

    int n   = blockIdx.z;
    int b0g = blockIdx.x * 128;
    int tid = threadIdx.x;
    int wid = tid >> 5, lane = tid & 31;
    int grp = lane >> 2, tig = lane & 3;
    int wm  = (wid >> 2) * 64;
    int wn  = (wid & 3) * 32;
    int am  = tid >> 1, ahs = tid & 1;

    const __half* A1n = g_se  + (size_t)n * BATCH * 128;
    const __half* A2n = g_oth + (size_t)n * BATCH * 128;
    const __half* Wtn = g_Wc1t + (size_t)n * 128 * 256;
    const float*  Wc2n = Wc2 + (size_t)n * 128 * 16;

    #pragma unroll
    for (int t = 0; t < 2; t++) {
        int f = tid + t * 256;
        *(float4*)&Wc2s[f * 4] = *(const float4*)&Wc2n[f * 4];
    }
    if (tid < 128) {
        bc1s[tid] = bc1[n * 128 + tid];
        rowacc[tid] = 0.f;
        const float* ap = actions + ((size_t)n * BATCH + b0g + tid) * 16;
        float best = ap[0]; int bi = 0;
        #pragma unroll
        for (int c = 1; c < 16; c++) { float v = ap[c]; if (v > best) { best = v; bi = c; } }
        amaxs[tid] = bi;
    }
    if (tid < 16) bc2s[tid] = bc2[n * 16 + tid];

    uint32_t sA = (uint32_t)__cvta_generic_to_shared(&As[0][0]);
    uint32_t sB = (uint32_t)__cvta_generic_to_shared(&Bs[0][0]);

    auto fill = [&](int kt) {
        int s = kt % STAGES;
        int k = kt * 16 + ahs * 8;
        const __half* asrc = (k < 128) ? (A1n + (size_t)(b0g + am) * 128 + k)
                                       : (A2n + (size_t)(b0g + am) * 128 + (k - 128));
        CPA16(sA + (s * 128 * SROW + am * SROW + ahs * 4) * 4, asrc);
        const __half* bsrc = Wtn + (size_t)am * 256 + k;
        CPA16(sB + (s * 128 * SROW + am * SROW + ahs * 4) * 4, bsrc);
        CP_COMMIT();
    };

    float acc[4][4][4];
    #pragma unroll
    for (int mt = 0; mt < 4; mt++)
        #pragma unroll
        for (int nt = 0; nt < 4; nt++)
            #pragma unroll
            for (int r = 0; r < 4; r++) acc[mt][nt][r] = 0.f;

    const int nkt = 16;
    fill(0);
    fill(1);

    for (int kt = 0; kt < nkt; kt++) {
        if (kt + 1 < nkt) { CP_WAIT1(); } else { CP_WAIT0(); }  // drain fix
        __syncthreads();
        const unsigned* Ab = As[kt % STAGES];
        const unsigned* Bb = Bs[kt % STAGES];
        unsigned af[4][4];
        #pragma unroll
        for (int mt = 0; mt < 4; mt++) {
            int m = wm + mt * 16 + grp;
            af[mt][0] = Ab[m * SROW + tig];
            af[mt][1] = Ab[(m + 8) * SROW + tig];
            af[mt][2] = Ab[m * SROW + tig + 4];
            af[mt][3] = Ab[(m + 8) * SROW + tig + 4];
        }
        unsigned bf[4][2];
        #pragma unroll
        for (int nt = 0; nt < 4; nt++) {
            int c = wn + nt * 8 + grp;
            bf[nt][0] = Bb[c * SROW + tig];
            bf[nt][1] = Bb[c * SROW + tig + 4];
        }
        #pragma unroll
        for (int mt = 0; mt < 4; mt++)
            #pragma unroll
            for (int nt = 0; nt < 4; nt++)
                MMA16(acc[mt][nt], af[mt][0], af[mt][1], af[mt][2], af[mt][3],
                      bf[nt][0], bf[nt][1]);
        if (kt + 2 < nkt) fill(kt + 2);
    }

    // fused epilogue: relu(h1)·Wc2[:,a] partial dots, quad-reduce, smem add
    #pragma unroll
    for (int mt = 0; mt < 4; mt++) {
        int row0 = wm + mt * 16 + grp;
        int a0 = amaxs[row0];
        int a1 = amaxs[row0 + 8];
        float p0 = 0.f, p1 = 0.f;
        #pragma unroll
        for (int nt = 0; nt < 4; nt++) {
            int col = wn + nt * 8 + tig * 2;
            float bj0 = bc1s[col], bj1 = bc1s[col + 1];
            float h00 = fmaxf(acc[mt][nt][0] + bj0, 0.f);
            float h01 = fmaxf(acc[mt][nt][1] + bj1, 0.f);
            float h10 = fmaxf(acc[mt][nt][2] + bj0, 0.f);
            float h11 = fmaxf(acc[mt][nt][3] + bj1, 0.f);
            p0 += h00 * Wc2s[col * 16 + a0] + h01 * Wc2s[(col + 1) * 16 + a0];
            p1 += h10 * Wc2s[col * 16 + a1] + h11 * Wc2s[(col + 1) * 16 + a1];
        }
        p0 += __shfl_xor_sync(0xffffffffu, p0, 1);
        p0 += __shfl_xor_sync(0xffffffffu, p0, 2);
        p1 += __shfl_xor_sync(0xffffffffu, p1, 1);
        p1 += __shfl_xor_sync(0xffffffffu, p1, 2);
        if (tig == 0) {
            atomicAdd(&rowacc[row0], p0);
            atomicAdd(&rowacc[row0 + 8], p1);
        }
    }
    __syncthreads();
    if (tid < 128)
        out[(size_t)n * BATCH + b0g + tid] = rowacc[tid] + bc2s[amaxs[tid]];
}

// ---------------- attention (fp32 math on fp16 inputs) -----------------------------
__global__ void __launch_bounds__(256)
attn_kernel()
{
    __shared__ float Ks[4 * 8 * 128];
    __shared__ float Vs[4 * 8 * 128];
    int tid = threadIdx.x;
    int b0  = blockIdx.x * 4;

    #pragma unroll
    for (int t = 0; t < 2; t++) {
        int f  = tid + t * 256;
        int c8 = f & 15;
        int rj = f >> 4;
        int r  = rj & 3, j = rj >> 2;
        size_t g = ((size_t)j * BATCH + b0 + r) * 128 + c8 * 8;
        int s = (r * 8 + j) * 128 + c8 * 8;
        uint4 uk = *(const uint4*)(g_Kb + g);
        uint4 uv = *(const uint4*)(g_Vb + g);
        const __half2* hk = (const __half2*)&uk;
        const __half2* hv = (const __half2*)&uv;
        #pragma unroll
        for (int p = 0; p < 4; p++) {
            float2 fk = __half22float2(hk[p]);
            float2 fv = __half22float2(hv[p]);
            Ks[s + p * 2]     = fk.x;
            Ks[s + p * 2 + 1] = fk.y;
            Vs[s + p * 2]     = fv.x;
            Vs[s + p * 2 + 1] = fv.y;
        }
    }
    __syncthreads();

    int hf = tid & 1;
    int i  = (tid >> 1) & 7;
    int k  = (tid >> 4) & 3;
    int r  = tid >> 6;

    float q[16];
    size_t base = ((size_t)i * BATCH + b0 + r) * 128 + k * 32 + hf * 16;
    {
        uint4 u0 = *(const uint4*)(g_Qb + base);
        uint4 u1 = *(const uint4*)(g_Qb + base + 8);
        const __half2* h0 = (const __half2*)&u0;
        const __half2* h1 = (const __half2*)&u1;
        #pragma unroll
        for (int p = 0; p < 4; p++) {
            float2 f0 = __half22float2(h0[p]);
            float2 f1 = __half22float2(h1[p]);
            q[p * 2] = f0.x; q[p * 2 + 1] = f0.y;
            q[8 + p * 2] = f1.x; q[8 + p * 2 + 1] = f1.y;
        }
    }

    float lg[8];
    #pragma unroll
    for (int j = 0; j < 8; j++) {
        const float* kp = &Ks[(r * 8 + j) * 128 + k * 32 + hf * 16];
        float d = 0.f;
        #pragma unroll
        for (int dd = 0; dd < 16; dd++) d += q[dd] * kp[dd];
        d += __shfl_xor_sync(0xffffffffu, d, 1);
        lg[j] = (j == i) ? -1e9f : d * 0.17677669529663687f;
    }
    float m = lg[0];
    #pragma unroll
    for (int j = 1; j < 8; j++) m = fmaxf(m, lg[j]);
    float ssum = 0.f;
    #pragma unroll
    for (int j = 0; j < 8; j++) { lg[j] = __expf(lg[j] - m); ssum += lg[j]; }
    float inv = 1.f / ssum;

    float acc[16];
    #pragma unroll
    for (int dd = 0; dd < 16; dd++) acc[dd] = 0.f;
    #pragma unroll
    for (int j = 0; j < 8; j++) {
        float p = lg[j] * inv;
        const float* vp = &Vs[(r * 8 + j) * 128 + k * 32 + hf * 16];
        #pragma unroll
        for (int dd = 0; dd < 16; dd++) acc[dd] += p * vp[dd];
    }
    {
        uint4 u0, u1;
        unsigned* w0 = (unsigned*)&u0;
        unsigned* w1 = (unsigned*)&u1;
        #pragma unroll
        for (int p = 0; p < 4; p++) {
            w0[p] = pkh2(acc[p * 2], acc[p * 2 + 1]);
            w1[p] = pkh2(acc[8 + p * 2], acc[8 + p * 2 + 1]);
        }
        *(uint4*)(g_oth + base)     = u0;
        *(uint4*)(g_oth + base + 8) = u1;
    }
}

// ---------------- launch -----------------------------------------------------------
extern "C" void kernel_launch(void* const* d_in, const int* in_sizes, int n_in,
                              void* d_out, int out_size)
{
    const float* states  = (const float*)d_in[0];
    const float* actions = (const float*)d_in[1];
    const float* We      = (const float*)d_in[2];
    const float* be      = (const float*)d_in[3];
    const float* Wse     = (const float*)d_in[4];
    const float* bs      = (const float*)d_in[5];
    const float* Wk      = (const float*)d_in[6];
    const float* Wq      = (const float*)d_in[7];
    const float* Wv      = (const float*)d_in[8];
    const float* bv      = (const float*)d_in[9];
    const float* Wc1     = (const float*)d_in[10];
    const float* bc1     = (const float*)d_in[11];
    const float* Wc2     = (const float*)d_in[12];
    const float* bc2     = (const float*)d_in[13];
    float* out = (float*)d_out;

    __half *p_sa, *p_se, *p_K, *p_Q, *p_V;
    __half *p_sth, *p_ach, *p_Wet, *p_Wst, *p_Wkt, *p_Wqt, *p_Wvt;
    cudaGetSymbolAddress((void**)&p_sa,  g_sa);
    cudaGetSymbolAddress((void**)&p_se,  g_se);
    cudaGetSymbolAddress((void**)&p_K,   g_Kb);
    cudaGetSymbolAddress((void**)&p_Q,   g_Qb);
    cudaGetSymbolAddress((void**)&p_V,   g_Vb);
    cudaGetSymbolAddress((void**)&p_sth, g_sth);
    cudaGetSymbolAddress((void**)&p_ach, g_ach);
    cudaGetSymbolAddress((void**)&p_Wet, g_Wet);
    cudaGetSymbolAddress((void**)&p_Wst, g_Wst);
    cudaGetSymbolAddress((void**)&p_Wkt, g_Wkt);
    cudaGetSymbolAddress((void**)&p_Wqt, g_Wqt);
    cudaGetSymbolAddress((void**)&p_Wvt, g_Wvt);

    // prep
    size_t ncvt = (size_t)NAG * BATCH * (SDIM + ADIM) / 8;
    cvt_inputs<<<(unsigned)((ncvt + 255) / 256), 256>>>(states, actions);
    int nw = NAG * 128 * 144 + NAG * 128 * 128 + 3 * 128 * 128 + NAG * 128 * 256;
    prep_weights<<<(nw + 255) / 256, 256>>>(We, Wse, Wk, Wq, Wv, Wc1);

    dim3 grid(BATCH / 128, 1, NAG);
    gemm16p<<<grid, 256>>>(p_sth, SDIM, p_ach, ADIM, p_Wet, 0, be, 0, 1, p_sa, SDIM + ADIM);
    gemm16p<<<grid, 256>>>(p_sth, SDIM, nullptr, 0,  p_Wst, 0, bs, 0, 1, p_se, SDIM);
    gemm16p<<<grid, 256>>>(p_sa, HID, nullptr, 0, p_Wkt, 1, nullptr, 1, 0, p_K, HID);
    gemm16p<<<grid, 256>>>(p_se, HID, nullptr, 0, p_Wqt, 1, nullptr, 1, 0, p_Q, HID);
    gemm16p<<<grid, 256>>>(p_sa, HID, nullptr, 0, p_Wvt, 1, bv,      1, 1, p_V, HID);
    attn_kernel<<<BATCH / 4, 256>>>();
    critic16p<<<grid, 256>>>(actions, bc1, Wc2, bc2, out);
}

// round 12
// speedup vs baseline: 1.7120x; 1.0383x over previous
#include <cuda_runtime.h>
#include <cuda_fp16.h>
#include <cstdint>

#define NAG   8
#define BATCH 32768
#define SDIM  128
#define ADIM  16
#define HID   128
#define HEADS 4
#define AD    32

// ---------------- scratch (device globals; no allocation allowed) ----------------
__device__ __half g_sa [(size_t)NAG * BATCH * HID];
__device__ __half g_se [(size_t)NAG * BATCH * HID];
__device__ __half g_Kb [(size_t)NAG * BATCH * HID];
__device__ __half g_Qb [(size_t)NAG * BATCH * HID];
__device__ __half g_Vb [(size_t)NAG * BATCH * HID];
__device__ __half g_oth[(size_t)NAG * BATCH * HID];
__device__ __half g_sth[(size_t)NAG * BATCH * SDIM];
__device__ __half g_ach[(size_t)NAG * BATCH * ADIM];
__device__ __half g_Wet [NAG * 128 * 144];
__device__ __half g_Wst [NAG * 128 * 128];
__device__ __half g_Wkt [128 * 128];
__device__ __half g_Wqt [128 * 128];
__device__ __half g_Wvt [128 * 128];
__device__ __half g_Wc1t[NAG * 128 * 256];

__device__ __forceinline__ unsigned pkh2(float a, float b) {
    __half2 h = __floats2half2_rn(a, b);
    return *(unsigned*)&h;
}

#define SROW 12          // 8 data words (16 halves) + 4 pad; frag banks bijective
#define GSTG 4           // GEMM pipeline stages (prefetch distance 3)
#define CSTG 3           // critic pipeline stages

#define MMA16(acc, a0, a1, a2, a3, b0, b1)                                        \
    asm("mma.sync.aligned.m16n8k16.row.col.f32.f16.f16.f32 "                      \
        "{%0,%1,%2,%3}, {%4,%5,%6,%7}, {%8,%9}, {%0,%1,%2,%3};"                   \
        : "+f"((acc)[0]), "+f"((acc)[1]), "+f"((acc)[2]), "+f"((acc)[3])          \
        : "r"(a0), "r"(a1), "r"(a2), "r"(a3), "r"(b0), "r"(b1))

#define CPA16(dst, src) \
    asm volatile("cp.async.cg.shared.global [%0], [%1], 16;\n" :: "r"(dst), "l"(src))
#define CP_COMMIT()  asm volatile("cp.async.commit_group;\n")
#define CP_WAIT2()   asm volatile("cp.async.wait_group 2;\n")
#define CP_WAIT1()   asm volatile("cp.async.wait_group 1;\n")
#define CP_WAIT0()   asm volatile("cp.async.wait_group 0;\n")

// ---------------- prep kernels ------------------------------------------------------
__global__ void cvt_inputs(const float* __restrict__ states,
                           const float* __restrict__ actions)
{
    size_t i  = (size_t)blockIdx.x * blockDim.x + threadIdx.x;
    size_t ns = (size_t)NAG * BATCH * SDIM / 8;
    size_t na = (size_t)NAG * BATCH * ADIM / 8;
    if (i < ns) {
        const float4* s = (const float4*)states + i * 2;
        float4 a = s[0], b = s[1];
        uint4 u = { pkh2(a.x, a.y), pkh2(a.z, a.w), pkh2(b.x, b.y), pkh2(b.z, b.w) };
        *(uint4*)(g_sth + i * 8) = u;
    } else if (i < ns + na) {
        size_t j = i - ns;
        const float4* s = (const float4*)actions + j * 2;
        float4 a = s[0], b = s[1];
        uint4 u = { pkh2(a.x, a.y), pkh2(a.z, a.w), pkh2(b.x, b.y), pkh2(b.z, b.w) };
        *(uint4*)(g_ach + j * 8) = u;
    }
}

__global__ void prep_weights(const float* __restrict__ We, const float* __restrict__ Ws,
                             const float* __restrict__ Wk, const float* __restrict__ Wq,
                             const float* __restrict__ Wv, const float* __restrict__ Wc1)
{
    int i = blockIdx.x * 256 + threadIdx.x;
    const int nWe = NAG * 128 * 144;
    const int nWs = NAG * 128 * 128;
    const int nH  = 128 * 128;
    const int nWc = NAG * 128 * 256;
    if (i < nWe) {
        int n = i / (128 * 144), r = i % (128 * 144);
        int c = r / 144, k = r % 144;
        g_Wet[i] = __float2half_rn(We[((size_t)n * 144 + k) * 128 + c]);
    } else if (i < nWe + nWs) {
        int j = i - nWe;
        int n = j / (128 * 128), r = j % (128 * 128);
        int c = r / 128, k = r % 128;
        g_Wst[j] = __float2half_rn(Ws[((size_t)n * 128 + k) * 128 + c]);
    } else if (i < nWe + nWs + 3 * nH) {
        int j = i - nWe - nWs;
        int which = j / nH, r = j % nH;
        int c = r / 128, k = r % 128;
        const float* W = which == 0 ? Wk : (which == 1 ? Wq : Wv);
        __half* D = which == 0 ? g_Wkt : (which == 1 ? g_Wqt : g_Wvt);
        D[r] = __float2half_rn(W[(size_t)(c >> 5) * (HID * AD) + (size_t)k * AD + (c & 31)]);
    } else if (i < nWe + nWs + 3 * nH + nWc) {
        int j = i - nWe - nWs - 3 * nH;
        int n = j / (128 * 256), r = j % (128 * 256);
        int c = r / 256, k = r % 256;
        g_Wc1t[j] = __float2half_rn(Wc1[((size_t)n * 256 + k) * 128 + c]);
    }
}

// ---------------- common GEMM core: 4-stage cp.async, 128x128, 8 warps -------------
// A1n/A2n/Wtn pre-resolved per agent; bn resolved bias base (or null).
__device__ __forceinline__ void gemm_core(
    const __half* A1n, int a1w, const __half* A2n, int a2w,
    const __half* Wtn, int Ktot,
    const float* bn, int dorelu, __half* Cn,
    unsigned (*As)[128 * SROW], unsigned (*Bs)[128 * SROW], int b0g)
{
    int tid = threadIdx.x;
    int wid = tid >> 5, lane = tid & 31;
    int grp = lane >> 2, tig = lane & 3;
    int wm  = (wid >> 2) * 64;
    int wn  = (wid & 3) * 32;
    int am  = tid >> 1, ahs = tid & 1;

    uint32_t sA = (uint32_t)__cvta_generic_to_shared(&As[0][0]);
    uint32_t sB = (uint32_t)__cvta_generic_to_shared(&Bs[0][0]);

    auto fill = [&](int kt) {
        int s  = kt % GSTG;
        int k  = kt * 16 + ahs * 8;
        const __half* asrc;
        if (k < a1w) asrc = A1n + (size_t)(b0g + am) * a1w + k;
        else         asrc = A2n + (size_t)(b0g + am) * a2w + (k - a1w);
        CPA16(sA + (s * 128 * SROW + am * SROW + ahs * 4) * 4, asrc);
        const __half* bsrc = Wtn + (size_t)am * Ktot + k;
        CPA16(sB + (s * 128 * SROW + am * SROW + ahs * 4) * 4, bsrc);
        CP_COMMIT();
    };

    float acc[4][4][4];
    #pragma unroll
    for (int mt = 0; mt < 4; mt++)
        #pragma unroll
        for (int nt = 0; nt < 4; nt++)
            #pragma unroll
            for (int r = 0; r < 4; r++) acc[mt][nt][r] = 0.f;

    int nkt = Ktot >> 4;
    fill(0); fill(1); fill(2);

    for (int kt = 0; kt < nkt; kt++) {
        int rem = nkt - 1 - kt;
        if (rem >= 2)      { CP_WAIT2(); }
        else if (rem == 1) { CP_WAIT1(); }
        else               { CP_WAIT0(); }
        __syncthreads();
        const unsigned* Ab = As[kt % GSTG];
        const unsigned* Bb = Bs[kt % GSTG];
        unsigned af[4][4];
        #pragma unroll
        for (int mt = 0; mt < 4; mt++) {
            int m = wm + mt * 16 + grp;
            af[mt][0] = Ab[m * SROW + tig];
            af[mt][1] = Ab[(m + 8) * SROW + tig];
            af[mt][2] = Ab[m * SROW + tig + 4];
            af[mt][3] = Ab[(m + 8) * SROW + tig + 4];
        }
        unsigned bf[4][2];
        #pragma unroll
        for (int nt = 0; nt < 4; nt++) {
            int c = wn + nt * 8 + grp;
            bf[nt][0] = Bb[c * SROW + tig];
            bf[nt][1] = Bb[c * SROW + tig + 4];
        }
        #pragma unroll
        for (int mt = 0; mt < 4; mt++)
            #pragma unroll
            for (int nt = 0; nt < 4; nt++)
                MMA16(acc[mt][nt], af[mt][0], af[mt][1], af[mt][2], af[mt][3],
                      bf[nt][0], bf[nt][1]);
        if (kt + 3 < nkt) fill(kt + 3);
    }

    #pragma unroll
    for (int nt = 0; nt < 4; nt++) {
        int col = wn + nt * 8 + tig * 2;
        float bj0 = bn ? bn[col]     : 0.f;
        float bj1 = bn ? bn[col + 1] : 0.f;
        #pragma unroll
        for (int mt = 0; mt < 4; mt++) {
            int row0 = b0g + wm + mt * 16 + grp;
            float v0 = acc[mt][nt][0] + bj0;
            float v1 = acc[mt][nt][1] + bj1;
            float v2 = acc[mt][nt][2] + bj0;
            float v3 = acc[mt][nt][3] + bj1;
            if (dorelu) {
                v0 = fmaxf(v0, 0.f); v1 = fmaxf(v1, 0.f);
                v2 = fmaxf(v2, 0.f); v3 = fmaxf(v3, 0.f);
            }
            *(__half2*)&Cn[(size_t)row0 * 128 + col]       = __floats2half2_rn(v0, v1);
            *(__half2*)&Cn[(size_t)(row0 + 8) * 128 + col] = __floats2half2_rn(v2, v3);
        }
    }
}

// ---------------- merged encoder launch: y=0 -> sa_enc (K=144), y=1 -> s_enc -------
__global__ void __launch_bounds__(256)
enc_kernel(const float* __restrict__ be, const float* __restrict__ bs)
{
    __shared__ __align__(16) unsigned As[GSTG][128 * SROW];
    __shared__ __align__(16) unsigned Bs[GSTG][128 * SROW];
    int n = blockIdx.z, b0g = blockIdx.x * 128;
    const __half* sthn = g_sth + (size_t)n * BATCH * SDIM;
    if (blockIdx.y == 0) {
        gemm_core(sthn, SDIM, g_ach + (size_t)n * BATCH * ADIM, ADIM,
                  g_Wet + (size_t)n * 128 * 144, 144,
                  be + n * 128, 1, g_sa + (size_t)n * BATCH * 128, As, Bs, b0g);
    } else {
        gemm_core(sthn, SDIM, sthn, SDIM,
                  g_Wst + (size_t)n * 128 * 128, 128,
                  bs + n * 128, 1, g_se + (size_t)n * BATCH * 128, As, Bs, b0g);
    }
}

// ---------------- merged K/Q/V launch: y=0 K, y=1 Q, y=2 V --------------------------
__global__ void __launch_bounds__(256)
kqv_kernel(const float* __restrict__ bv)
{
    __shared__ __align__(16) unsigned As[GSTG][128 * SROW];
    __shared__ __align__(16) unsigned Bs[GSTG][128 * SROW];
    int n = blockIdx.z, b0g = blockIdx.x * 128;
    const __half* san = g_sa + (size_t)n * BATCH * 128;
    const __half* sen = g_se + (size_t)n * BATCH * 128;
    if (blockIdx.y == 0) {
        gemm_core(san, HID, san, HID, g_Wkt, 128,
                  nullptr, 0, g_Kb + (size_t)n * BATCH * 128, As, Bs, b0g);
    } else if (blockIdx.y == 1) {
        gemm_core(sen, HID, sen, HID, g_Wqt, 128,
                  nullptr, 0, g_Qb + (size_t)n * BATCH * 128, As, Bs, b0g);
    } else {
        gemm_core(san, HID, san, HID, g_Wvt, 128,
                  bv, 1, g_Vb + (size_t)n * BATCH * 128, As, Bs, b0g);
    }
}

// ---------------- pipelined fused critic (3 stages; proven R11 code) ---------------
__global__ void __launch_bounds__(256)
critic16p(const float* __restrict__ actions,
          const float* __restrict__ bc1, const float* __restrict__ Wc2,
          const float* __restrict__ bc2, float* __restrict__ out)
{
    __shared__ __align__(16) unsigned As[CSTG][128 * SROW];
    __shared__ __align__(16) unsigned Bs[CSTG][128 * SROW];
    __shared__ float Wc2s[128 * 16];
    __shared__ float bc1s[128];
    __shared__ float bc2s[16];
    __shared__ float rowacc[128];
    __shared__ int   amaxs[128];

    int n   = blockIdx.z;
    int b0g = blockIdx.x * 128;
    int tid = threadIdx.x;
    int wid = tid >> 5, lane = tid & 31;
    int grp = lane >> 2, tig = lane & 3;
    int wm  = (wid >> 2) * 64;
    int wn  = (wid & 3) * 32;
    int am  = tid >> 1, ahs = tid & 1;

    const __half* A1n = g_se  + (size_t)n * BATCH * 128;
    const __half* A2n = g_oth + (size_t)n * BATCH * 128;
    const __half* Wtn = g_Wc1t + (size_t)n * 128 * 256;
    const float*  Wc2n = Wc2 + (size_t)n * 128 * 16;

    #pragma unroll
    for (int t = 0; t < 2; t++) {
        int f = tid + t * 256;
        *(float4*)&Wc2s[f * 4] = *(const float4*)&Wc2n[f * 4];
    }
    if (tid < 128) {
        bc1s[tid] = bc1[n * 128 + tid];
        rowacc[tid] = 0.f;
        const float* ap = actions + ((size_t)n * BATCH + b0g + tid) * 16;
        float best = ap[0]; int bi = 0;
        #pragma unroll
        for (int c = 1; c < 16; c++) { float v = ap[c]; if (v > best) { best = v; bi = c; } }
        amaxs[tid] = bi;
    }
    if (tid < 16) bc2s[tid] = bc2[n * 16 + tid];

    uint32_t sA = (uint32_t)__cvta_generic_to_shared(&As[0][0]);
    uint32_t sB = (uint32_t)__cvta_generic_to_shared(&Bs[0][0]);

    auto fill = [&](int kt) {
        int s = kt % CSTG;
        int k = kt * 16 + ahs * 8;
        const __half* asrc = (k < 128) ? (A1n + (size_t)(b0g + am) * 128 + k)
                                       : (A2n + (size_t)(b0g + am) * 128 + (k - 128));
        CPA16(sA + (s * 128 * SROW + am * SROW + ahs * 4) * 4, asrc);
        const __half* bsrc = Wtn + (size_t)am * 256 + k;
        CPA16(sB + (s * 128 * SROW + am * SROW + ahs * 4) * 4, bsrc);
        CP_COMMIT();
    };

    float acc[4][4][4];
    #pragma unroll
    for (int mt = 0; mt < 4; mt++)
        #pragma unroll
        for (int nt = 0; nt < 4; nt++)
            #pragma unroll
            for (int r = 0; r < 4; r++) acc[mt][nt][r] = 0.f;

    const int nkt = 16;
    fill(0);
    fill(1);

    for (int kt = 0; kt < nkt; kt++) {
        if (kt + 1 < nkt) { CP_WAIT1(); } else { CP_WAIT0(); }
        __syncthreads();
        const unsigned* Ab = As[kt % CSTG];
        const unsigned* Bb = Bs[kt % CSTG];
        unsigned af[4][4];
        #pragma unroll
        for (int mt = 0; mt < 4; mt++) {
            int m = wm + mt * 16 + grp;
            af[mt][0] = Ab[m * SROW + tig];
            af[mt][1] = Ab[(m + 8) * SROW + tig];
            af[mt][2] = Ab[m * SROW + tig + 4];
            af[mt][3] = Ab[(m + 8) * SROW + tig + 4];
        }
        unsigned bf[4][2];
        #pragma unroll
        for (int nt = 0; nt < 4; nt++) {
            int c = wn + nt * 8 + grp;
            bf[nt][0] = Bb[c * SROW + tig];
            bf[nt][1] = Bb[c * SROW + tig + 4];
        }
        #pragma unroll
        for (int mt = 0; mt < 4; mt++)
            #pragma unroll
            for (int nt = 0; nt < 4; nt++)
                MMA16(acc[mt][nt], af[mt][0], af[mt][1], af[mt][2], af[mt][3],
                      bf[nt][0], bf[nt][1]);
        if (kt + 2 < nkt) fill(kt + 2);
    }

    #pragma unroll
    for (int mt = 0; mt < 4; mt++) {
        int row0 = wm + mt * 16 + grp;
        int a0 = amaxs[row0];
        int a1 = amaxs[row0 + 8];
        float p0 = 0.f, p1 = 0.f;
        #pragma unroll
        for (int nt = 0; nt < 4; nt++) {
            int col = wn + nt * 8 + tig * 2;
            float bj0 = bc1s[col], bj1 = bc1s[col + 1];
            float h00 = fmaxf(acc[mt][nt][0] + bj0, 0.f);
            float h01 = fmaxf(acc[mt][nt][1] + bj1, 0.f);
            float h10 = fmaxf(acc[mt][nt][2] + bj0, 0.f);
            float h11 = fmaxf(acc[mt][nt][3] + bj1, 0.f);
            p0 += h00 * Wc2s[col * 16 + a0] + h01 * Wc2s[(col + 1) * 16 + a0];
            p1 += h10 * Wc2s[col * 16 + a1] + h11 * Wc2s[(col + 1) * 16 + a1];
        }
        p0 += __shfl_xor_sync(0xffffffffu, p0, 1);
        p0 += __shfl_xor_sync(0xffffffffu, p0, 2);
        p1 += __shfl_xor_sync(0xffffffffu, p1, 1);
        p1 += __shfl_xor_sync(0xffffffffu, p1, 2);
        if (tig == 0) {
            atomicAdd(&rowacc[row0], p0);
            atomicAdd(&rowacc[row0 + 8], p1);
        }
    }
    __syncthreads();
    if (tid < 128)
        out[(size_t)n * BATCH + b0g + tid] = rowacc[tid] + bc2s[amaxs[tid]];
}

// ---------------- attention (unchanged R11) ----------------------------------------
__global__ void __launch_bounds__(256)
attn_kernel()
{
    __shared__ float Ks[4 * 8 * 128];
    __shared__ float Vs[4 * 8 * 128];
    int tid = threadIdx.x;
    int b0  = blockIdx.x * 4;

    #pragma unroll
    for (int t = 0; t < 2; t++) {
        int f  = tid + t * 256;
        int c8 = f & 15;
        int rj = f >> 4;
        int r  = rj & 3, j = rj >> 2;
        size_t g = ((size_t)j * BATCH + b0 + r) * 128 + c8 * 8;
        int s = (r * 8 + j) * 128 + c8 * 8;
        uint4 uk = *(const uint4*)(g_Kb + g);
        uint4 uv = *(const uint4*)(g_Vb + g);
        const __half2* hk = (const __half2*)&uk;
        const __half2* hv = (const __half2*)&uv;
        #pragma unroll
        for (int p = 0; p < 4; p++) {
            float2 fk = __half22float2(hk[p]);
            float2 fv = __half22float2(hv[p]);
            Ks[s + p * 2]     = fk.x;
            Ks[s + p * 2 + 1] = fk.y;
            Vs[s + p * 2]     = fv.x;
            Vs[s + p * 2 + 1] = fv.y;
        }
    }
    __syncthreads();

    int hf = tid & 1;
    int i  = (tid >> 1) & 7;
    int k  = (tid >> 4) & 3;
    int r  = tid >> 6;

    float q[16];
    size_t base = ((size_t)i * BATCH + b0 + r) * 128 + k * 32 + hf * 16;
    {
        uint4 u0 = *(const uint4*)(g_Qb + base);
        uint4 u1 = *(const uint4*)(g_Qb + base + 8);
        const __half2* h0 = (const __half2*)&u0;
        const __half2* h1 = (const __half2*)&u1;
        #pragma unroll
        for (int p = 0; p < 4; p++) {
            float2 f0 = __half22float2(h0[p]);
            float2 f1 = __half22float2(h1[p]);
            q[p * 2] = f0.x; q[p * 2 + 1] = f0.y;
            q[8 + p * 2] = f1.x; q[8 + p * 2 + 1] = f1.y;
        }
    }

    float lg[8];
    #pragma unroll
    for (int j = 0; j < 8; j++) {
        const float* kp = &Ks[(r * 8 + j) * 128 + k * 32 + hf * 16];
        float d = 0.f;
        #pragma unroll
        for (int dd = 0; dd < 16; dd++) d += q[dd] * kp[dd];
        d += __shfl_xor_sync(0xffffffffu, d, 1);
        lg[j] = (j == i) ? -1e9f : d * 0.17677669529663687f;
    }
    float m = lg[0];
    #pragma unroll
    for (int j = 1; j < 8; j++) m = fmaxf(m, lg[j]);
    float ssum = 0.f;
    #pragma unroll
    for (int j = 0; j < 8; j++) { lg[j] = __expf(lg[j] - m); ssum += lg[j]; }
    float inv = 1.f / ssum;

    float acc[16];
    #pragma unroll
    for (int dd = 0; dd < 16; dd++) acc[dd] = 0.f;
    #pragma unroll
    for (int j = 0; j < 8; j++) {
        float p = lg[j] * inv;
        const float* vp = &Vs[(r * 8 + j) * 128 + k * 32 + hf * 16];
        #pragma unroll
        for (int dd = 0; dd < 16; dd++) acc[dd] += p * vp[dd];
    }
    {
        uint4 u0, u1;
        unsigned* w0 = (unsigned*)&u0;
        unsigned* w1 = (unsigned*)&u1;
        #pragma unroll
        for (int p = 0; p < 4; p++) {
            w0[p] = pkh2(acc[p * 2], acc[p * 2 + 1]);
            w1[p] = pkh2(acc[8 + p * 2], acc[8 + p * 2 + 1]);
        }
        *(uint4*)(g_oth + base)     = u0;
        *(uint4*)(g_oth + base + 8) = u1;
    }
}

// ---------------- launch -----------------------------------------------------------
extern "C" void kernel_launch(void* const* d_in, const int* in_sizes, int n_in,
                              void* d_out, int out_size)
{
    const float* states  = (const float*)d_in[0];
    const float* actions = (const float*)d_in[1];
    const float* We      = (const float*)d_in[2];
    const float* be      = (const float*)d_in[3];
    const float* Wse     = (const float*)d_in[4];
    const float* bs      = (const float*)d_in[5];
    const float* Wk      = (const float*)d_in[6];
    const float* Wq      = (const float*)d_in[7];
    const float* Wv      = (const float*)d_in[8];
    const float* bv      = (const float*)d_in[9];
    const float* Wc1     = (const float*)d_in[10];
    const float* bc1     = (const float*)d_in[11];
    const float* Wc2     = (const float*)d_in[12];
    const float* bc2     = (const float*)d_in[13];
    float* out = (float*)d_out;

    size_t ncvt = (size_t)NAG * BATCH * (SDIM + ADIM) / 8;
    cvt_inputs<<<(unsigned)((ncvt + 255) / 256), 256>>>(states, actions);
    int nw = NAG * 128 * 144 + NAG * 128 * 128 + 3 * 128 * 128 + NAG * 128 * 256;
    prep_weights<<<(nw + 255) / 256, 256>>>(We, Wse, Wk, Wq, Wv, Wc1);

    enc_kernel<<<dim3(BATCH / 128, 2, NAG), 256>>>(be, bs);
    kqv_kernel<<<dim3(BATCH / 128, 3, NAG), 256>>>(bv);
    attn_kernel<<<BATCH / 4, 256>>>();
    critic16p<<<dim3(BATCH / 128, 1, NAG), 256>>>(actions, bc1, Wc2, bc2, out);
}